// round 1
// baseline (speedup 1.0000x reference)
#include <cuda_runtime.h>
#include <cstdint>

#define LQ 512
#define HID 400
#define GATES 1600      // 4*HID
#define G_CTAS 25       // CTAs per direction in the scan
#define UNITS_PER_CTA 16
#define KK 13           // ceil(400/32) k-slices per lane

// ---------------- scratch (allocation-free: __device__ globals) ----------------
__device__ float    g_x0[LQ * 400];          // embedded input [t][400]
__device__ float    g_xi[2 * LQ * GATES];    // input projections [dir][t][1600] (reused across layers)
__device__ float    g_H0[LQ * 800];          // layer0 output [t][fwd400|bwd400]
__device__ float    g_H1[LQ * 800];          // layer1 output
__device__ float    g_hbuf[2 * 2 * 416];     // [dir][parity][416] h broadcast (pad zeros)
__device__ unsigned g_flag[2 * 2 * 32];      // [layer][dir][cta] step flags
__device__ float    g_sv[LQ], g_tv[LQ];

// ---------------- embedding gather + flag reset ----------------
__global__ void embed_k(const int* __restrict__ wi, const int* __restrict__ ti,
                        const float* __restrict__ we, const float* __restrict__ te)
{
    int t = blockIdx.x;
    int tid = threadIdx.x;
    if (t == 0 && tid < 128) g_flag[tid] = 0u;   // reset all scan flags each replay
    const float* wr = we + (size_t)wi[t] * 300;
    for (int k = tid; k < 300; k += 128) g_x0[t * 400 + k] = wr[k];
    const float* tr = te + (size_t)ti[t] * 100;
    if (tid < 100) g_x0[t * 400 + 300 + tid] = tr[tid];
}

// ---------------- xi GEMM: out[dir][t][n] = sum_k A[t][k]*W[dir][n][k] + bih+bhh ----------------
__global__ void __launch_bounds__(256) gemm_k(int layer,
        const float* __restrict__ W,    // [2][1600][K]
        const float* __restrict__ bih,  // [2][1600]
        const float* __restrict__ bhh)  // [2][1600]
{
    const int K = layer ? 800 : 400;
    const float* A = layer ? g_H0 : g_x0;
    int dir = blockIdx.z;
    int n0 = blockIdx.x * 64;
    int m0 = blockIdx.y * 64;
    const float* B = W + (size_t)dir * GATES * K;

    __shared__ float As[64][17];
    __shared__ float Bs[64][17];
    int tid = threadIdx.x;
    int lr = tid >> 2;
    int lc = (tid & 3) * 4;
    int tx = tid & 15, ty = tid >> 4;
    float acc[4][4] = {};

    for (int kt = 0; kt < K; kt += 16) {
        float4 av = *(const float4*)(A + (size_t)(m0 + lr) * K + kt + lc);
        float4 bv = *(const float4*)(B + (size_t)(n0 + lr) * K + kt + lc);
        As[lr][lc + 0] = av.x; As[lr][lc + 1] = av.y; As[lr][lc + 2] = av.z; As[lr][lc + 3] = av.w;
        Bs[lr][lc + 0] = bv.x; Bs[lr][lc + 1] = bv.y; Bs[lr][lc + 2] = bv.z; Bs[lr][lc + 3] = bv.w;
        __syncthreads();
#pragma unroll
        for (int kk = 0; kk < 16; ++kk) {
            float a[4], b[4];
#pragma unroll
            for (int i = 0; i < 4; ++i) a[i] = As[ty * 4 + i][kk];
#pragma unroll
            for (int jj = 0; jj < 4; ++jj) b[jj] = Bs[tx * 4 + jj][kk];
#pragma unroll
            for (int i = 0; i < 4; ++i)
#pragma unroll
                for (int jj = 0; jj < 4; ++jj) acc[i][jj] += a[i] * b[jj];
        }
        __syncthreads();
    }
#pragma unroll
    for (int jj = 0; jj < 4; ++jj) {
        int n = n0 + tx * 4 + jj;
        float bias = bih[dir * GATES + n] + bhh[dir * GATES + n];
#pragma unroll
        for (int i = 0; i < 4; ++i) {
            int m = m0 + ty * 4 + i;
            g_xi[((size_t)dir * LQ + m) * GATES + n] = acc[i][jj] + bias;
        }
    }
}

// ---------------- persistent LSTM scan (both directions, 50 CTAs) ----------------
__global__ void __launch_bounds__(512, 1) scan_k(int layer, const float* __restrict__ Whh)
{
    int dir = blockIdx.x / G_CTAS;
    int cta = blockIdx.x % G_CTAS;
    int w  = threadIdx.x >> 5;
    int ld = threadIdx.x & 31;
    int j  = cta * UNITS_PER_CTA + w;     // this warp's hidden unit

    // register-resident recurrent weights: 4 gate rows of unit j, lane-strided k
    float wreg[4][KK];
#pragma unroll
    for (int g = 0; g < 4; ++g) {
        const float* wr = Whh + ((size_t)dir * GATES + g * HID + j) * HID;
#pragma unroll
        for (int kk = 0; kk < KK; ++kk) {
            int k = ld + kk * 32;
            wreg[g][kk] = (k < HID) ? wr[k] : 0.f;
        }
    }

    const float* xid = g_xi + (size_t)dir * LQ * GATES;
    float* Hout = layer ? g_H1 : g_H0;
    unsigned* flg = g_flag + (layer * 2 + dir) * 32;
    float c = 0.f;

    for (int s = 0; s < LQ; ++s) {
        int t = dir ? (LQ - 1 - s) : s;
        // prefetch xi for this step BEFORE waiting on the barrier
        const float* xr = xid + (size_t)t * GATES + j;
        float xv0 = __ldg(xr);
        float xv1 = __ldg(xr + HID);
        float xv2 = __ldg(xr + 2 * HID);
        float xv3 = __ldg(xr + 3 * HID);

        float a0 = 0.f, a1 = 0.f, a2 = 0.f, a3 = 0.f;
        if (s > 0) {
            if (w == 0) {   // warp 0 polls all 25 CTA flags
                unsigned target = (unsigned)s;
                unsigned v = target;
                bool ok;
                do {
                    if (ld < G_CTAS)
                        asm volatile("ld.global.acquire.gpu.u32 %0, [%1];"
                                     : "=r"(v) : "l"(flg + ld) : "memory");
                    ok = __all_sync(0xffffffffu, v >= target);
                } while (!ok);
            }
            __syncthreads();
            const float* hr = g_hbuf + (dir * 2 + ((s + 1) & 1)) * 416 + ld;  // read parity (s-1)&1
            float hv[KK];
#pragma unroll
            for (int kk = 0; kk < KK; ++kk) hv[kk] = __ldcg(hr + kk * 32);
#pragma unroll
            for (int kk = 0; kk < KK; ++kk) {
                a0 += wreg[0][kk] * hv[kk];
                a1 += wreg[1][kk] * hv[kk];
                a2 += wreg[2][kk] * hv[kk];
                a3 += wreg[3][kk] * hv[kk];
            }
        }
        // warp butterfly reduce the 4 gate dot-products
#pragma unroll
        for (int o = 16; o; o >>= 1) {
            a0 += __shfl_xor_sync(0xffffffffu, a0, o);
            a1 += __shfl_xor_sync(0xffffffffu, a1, o);
            a2 += __shfl_xor_sync(0xffffffffu, a2, o);
            a3 += __shfl_xor_sync(0xffffffffu, a3, o);
        }
        a0 += xv0; a1 += xv1; a2 += xv2; a3 += xv3;

        float iv = 1.f / (1.f + __expf(-a0));
        float fv = 1.f / (1.f + __expf(-a1));
        float gv = tanhf(a2);
        float ov = 1.f / (1.f + __expf(-a3));
        c = fv * c + iv * gv;
        float h = ov * tanhf(c);

        if (ld == 0) {
            __stcg(g_hbuf + (dir * 2 + (s & 1)) * 416 + j, h);   // write parity s&1
            Hout[(size_t)t * 800 + dir * HID + j] = h;
        }
        __syncthreads();
        if (threadIdx.x == 0) {
            __threadfence();
            asm volatile("st.global.release.gpu.u32 [%0], %1;"
                         :: "l"(flg + cta), "r"((unsigned)(s + 1)) : "memory");
        }
    }
}

// ---------------- head/dep projections: sv[i]=h_i . w[:800], tv[i]=h_i . w[800:] ----------------
__global__ void headdep_k(const float* __restrict__ fw)
{
    int i = blockIdx.x;
    const float* hr = g_H1 + (size_t)i * 800;
    float a = 0.f, b = 0.f;
    for (int k = threadIdx.x; k < 800; k += 256) {
        float h = hr[k];
        a += h * __ldg(fw + k);
        b += h * __ldg(fw + 800 + k);
    }
#pragma unroll
    for (int o = 16; o; o >>= 1) {
        a += __shfl_xor_sync(0xffffffffu, a, o);
        b += __shfl_xor_sync(0xffffffffu, b, o);
    }
    __shared__ float sa[8], sb[8];
    int w = threadIdx.x >> 5, ld = threadIdx.x & 31;
    if (ld == 0) { sa[w] = a; sb[w] = b; }
    __syncthreads();
    if (threadIdx.x == 0) {
        float A = 0.f, B = 0.f;
#pragma unroll
        for (int q = 0; q < 8; ++q) { A += sa[q]; B += sb[q]; }
        g_sv[i] = A; g_tv[i] = B;
    }
}

// ---------------- pairwise scores: out[i*L+j] = tanh(sv[i]+tv[j]+b) ----------------
__global__ void scores_k(const float* __restrict__ fb, float* __restrict__ out)
{
    int i = blockIdx.x, jj = threadIdx.x;
    out[(size_t)i * LQ + jj] = tanhf(g_sv[i] + g_tv[jj] + fb[0]);
}

// ---------------- launch ----------------
extern "C" void kernel_launch(void* const* d_in, const int* in_sizes, int n_in,
                              void* d_out, int out_size)
{
    // inputs: words, tags, [max_length scalar?], word_emb, tag_emb,
    //         wih0, whh0, bih0, bhh0, wih1, whh1, bih1, bhh1, fc1_w, fc1_b
    int base = (in_sizes[2] == 1) ? 3 : 2;
    const int*   wi   = (const int*)d_in[0];
    const int*   ti   = (const int*)d_in[1];
    const float* we   = (const float*)d_in[base + 0];
    const float* te   = (const float*)d_in[base + 1];
    const float* wih0 = (const float*)d_in[base + 2];
    const float* whh0 = (const float*)d_in[base + 3];
    const float* bih0 = (const float*)d_in[base + 4];
    const float* bhh0 = (const float*)d_in[base + 5];
    const float* wih1 = (const float*)d_in[base + 6];
    const float* whh1 = (const float*)d_in[base + 7];
    const float* bih1 = (const float*)d_in[base + 8];
    const float* bhh1 = (const float*)d_in[base + 9];
    const float* fw   = (const float*)d_in[base + 10];
    const float* fb   = (const float*)d_in[base + 11];
    float* out = (float*)d_out;

    embed_k<<<LQ, 128>>>(wi, ti, we, te);
    dim3 gg(GATES / 64, LQ / 64, 2);
    gemm_k<<<gg, 256>>>(0, wih0, bih0, bhh0);
    scan_k<<<2 * G_CTAS, 512>>>(0, whh0);
    gemm_k<<<gg, 256>>>(1, wih1, bih1, bhh1);
    scan_k<<<2 * G_CTAS, 512>>>(1, whh1);
    headdep_k<<<LQ, 256>>>(fw);
    scores_k<<<LQ, LQ>>>(fb, out);
}

// round 2
// speedup vs baseline: 1.6317x; 1.6317x over previous
#include <cuda_runtime.h>
#include <cstdint>

#define LQ 512
#define HID 400
#define GATES 1600
#define CLUST 16        // CTAs per direction (one cluster)
#define UPC 25          // hidden units per CTA
#define THREADS 416     // 13 warps, 2 units/warp (warp 12 has 1)
#define HPAD 448        // padded h vector (float), per parity

// ---------------- scratch ----------------
__device__ float g_x0[LQ * 400];
__device__ float g_xi[2 * LQ * GATES];
__device__ float g_H0[LQ * 800];
__device__ float g_H1[LQ * 800];
__device__ float g_sv[LQ], g_tv[LQ];

// ---------------- helpers ----------------
__device__ __forceinline__ unsigned long long pk2(float lo, float hi) {
    unsigned long long r;
    asm("mov.b64 %0,{%1,%2};" : "=l"(r) : "f"(lo), "f"(hi));
    return r;
}
__device__ __forceinline__ void upk2(unsigned long long v, float& lo, float& hi) {
    asm("mov.b64 {%0,%1},%2;" : "=f"(lo), "=f"(hi) : "l"(v));
}
__device__ __forceinline__ void fma2(unsigned long long& d, unsigned long long a, unsigned long long b) {
    asm("fma.rn.f32x2 %0,%1,%2,%3;" : "=l"(d) : "l"(a), "l"(b), "l"(d));
}

// ---------------- embedding gather ----------------
__global__ void embed_k(const int* __restrict__ wi, const int* __restrict__ ti,
                        const float* __restrict__ we, const float* __restrict__ te)
{
    int t = blockIdx.x;
    int tid = threadIdx.x;
    const float* wr = we + (size_t)wi[t] * 300;
    for (int k = tid; k < 300; k += 128) g_x0[t * 400 + k] = wr[k];
    const float* tr = te + (size_t)ti[t] * 100;
    if (tid < 100) g_x0[t * 400 + 300 + tid] = tr[tid];
}

// ---------------- xi GEMM ----------------
__global__ void __launch_bounds__(256) gemm_k(int layer,
        const float* __restrict__ W,
        const float* __restrict__ bih,
        const float* __restrict__ bhh)
{
    const int K = layer ? 800 : 400;
    const float* A = layer ? g_H0 : g_x0;
    int dir = blockIdx.z;
    int n0 = blockIdx.x * 64;
    int m0 = blockIdx.y * 64;
    const float* B = W + (size_t)dir * GATES * K;

    __shared__ float As[64][17];
    __shared__ float Bs[64][17];
    int tid = threadIdx.x;
    int lr = tid >> 2;
    int lc = (tid & 3) * 4;
    int tx = tid & 15, ty = tid >> 4;
    float acc[4][4] = {};

    for (int kt = 0; kt < K; kt += 16) {
        float4 av = *(const float4*)(A + (size_t)(m0 + lr) * K + kt + lc);
        float4 bv = *(const float4*)(B + (size_t)(n0 + lr) * K + kt + lc);
        As[lr][lc + 0] = av.x; As[lr][lc + 1] = av.y; As[lr][lc + 2] = av.z; As[lr][lc + 3] = av.w;
        Bs[lr][lc + 0] = bv.x; Bs[lr][lc + 1] = bv.y; Bs[lr][lc + 2] = bv.z; Bs[lr][lc + 3] = bv.w;
        __syncthreads();
#pragma unroll
        for (int kk = 0; kk < 16; ++kk) {
            float a[4], b[4];
#pragma unroll
            for (int i = 0; i < 4; ++i) a[i] = As[ty * 4 + i][kk];
#pragma unroll
            for (int jj = 0; jj < 4; ++jj) b[jj] = Bs[tx * 4 + jj][kk];
#pragma unroll
            for (int i = 0; i < 4; ++i)
#pragma unroll
                for (int jj = 0; jj < 4; ++jj) acc[i][jj] += a[i] * b[jj];
        }
        __syncthreads();
    }
#pragma unroll
    for (int jj = 0; jj < 4; ++jj) {
        int n = n0 + tx * 4 + jj;
        float bias = bih[dir * GATES + n] + bhh[dir * GATES + n];
#pragma unroll
        for (int i = 0; i < 4; ++i) {
            int m = m0 + ty * 4 + i;
            g_xi[((size_t)dir * LQ + m) * GATES + n] = acc[i][jj] + bias;
        }
    }
}

// ---------------- cluster LSTM scan ----------------
__global__ void __launch_bounds__(THREADS, 1) __cluster_dims__(CLUST, 1, 1)
scan_k(int layer, const float* __restrict__ Whh)
{
    __shared__ __align__(16) float h_loc[2 * HPAD];   // [parity][448]

    int dir = blockIdx.x >> 4;
    unsigned rank;
    asm("mov.u32 %0, %%cluster_ctarank;" : "=r"(rank));
    int w  = threadIdx.x >> 5;
    int ld = threadIdx.x & 31;

    for (int i = threadIdx.x; i < 2 * HPAD; i += THREADS) h_loc[i] = 0.f;

    // ---- register-resident recurrent weights (2 units x 4 gates x 7 f32x2) ----
    unsigned long long wt[2][4][7];
    int uA = 2 * w, uB = 2 * w + 1;
    bool vB = (uB < UPC);
    int guA = rank * UPC + uA;
    int guB = rank * UPC + uB;
#pragma unroll
    for (int u = 0; u < 2; ++u) {
        bool vu = u ? vB : true;
        int gu = u ? (vu ? guB : guA) : guA;
#pragma unroll
        for (int g = 0; g < 4; ++g) {
            const float* row = Whh + ((size_t)(dir * GATES + g * HID + gu)) * HID;
#pragma unroll
            for (int kk = 0; kk < 7; ++kk) {
                int k = 2 * ld + 64 * kk;
                float lo = 0.f, hi = 0.f;
                if (vu && k < HID) { lo = row[k]; hi = row[k + 1]; }
                wt[u][g][kk] = pk2(lo, hi);
            }
        }
    }

    // ---- precompute DSMEM store address (lane -> rank ld>>1, unit ld&1) ----
    unsigned hbase;
    asm("{ .reg .u64 t; cvta.to.shared.u64 t, %1; cvt.u32.u64 %0, t; }"
        : "=r"(hbase) : "l"(h_loc));
    unsigned rrank = (unsigned)(ld >> 1);
    unsigned rbase;
    asm("mapa.shared::cluster.u32 %0, %1, %2;" : "=r"(rbase) : "r"(hbase), "r"(rrank));
    int usel = ld & 1;
    int lu_st = 2 * w + usel;
    bool st_valid = (lu_st < UPC);
    unsigned st_off0 = rbase + (unsigned)((rank * UPC + lu_st) * 4);

    // ---- lane-parallel xi address: lane's value j = (ld>>2)&7 ----
    int j    = (ld >> 2) & 7;
    int gate = j & 3;
    int un   = j >> 2;
    bool vx  = (2 * w + un) < UPC;
    int gux  = rank * UPC + 2 * w + (vx ? un : 0);
    const float* xid = g_xi + (size_t)dir * LQ * GATES + gate * HID + gux;

    float* Hout = layer ? g_H1 : g_H0;
    float cA = 0.f, cB = 0.f;
    bool b4 = (ld & 16), b3 = (ld & 8), b2 = (ld & 4);
    const float2* hp = (const float2*)h_loc;

    asm volatile("barrier.cluster.arrive.aligned;" ::: "memory");
    asm volatile("barrier.cluster.wait.aligned;"  ::: "memory");

    for (int s = 0; s < LQ; ++s) {
        int t = dir ? (LQ - 1 - s) : s;
        float xig = __ldg(xid + (size_t)t * GATES);

        // read h_{s-1} from LOCAL smem (parity (s+1)&1), packed pairs
        const float2* hrow = hp + ((s + 1) & 1) * (HPAD / 2) + ld;
        unsigned long long acc[2][4] = {};
#pragma unroll
        for (int kk = 0; kk < 7; ++kk) {
            float2 h2 = hrow[kk * 32];
            unsigned long long hv = pk2(h2.x, h2.y);
            fma2(acc[0][0], wt[0][0][kk], hv);
            fma2(acc[0][1], wt[0][1][kk], hv);
            fma2(acc[0][2], wt[0][2][kk], hv);
            fma2(acc[0][3], wt[0][3][kk], hv);
            fma2(acc[1][0], wt[1][0][kk], hv);
            fma2(acc[1][1], wt[1][1][kk], hv);
            fma2(acc[1][2], wt[1][2][kk], hv);
            fma2(acc[1][3], wt[1][3][kk], hv);
        }
        float v[8];
#pragma unroll
        for (int u = 0; u < 2; ++u)
#pragma unroll
            for (int g = 0; g < 4; ++g) {
                float lo, hi; upk2(acc[u][g], lo, hi);
                v[u * 4 + g] = lo + hi;
            }

        // 3-level value-merging butterfly: value j ends in lanes (ld>>2)&7 == j
        float wv[4];
#pragma unroll
        for (int k = 0; k < 4; ++k) {
            float keep = b4 ? v[k + 4] : v[k];
            float send = b4 ? v[k] : v[k + 4];
            wv[k] = keep + __shfl_xor_sync(0xffffffffu, send, 16);
        }
        float uv[2];
#pragma unroll
        for (int k = 0; k < 2; ++k) {
            float keep = b3 ? wv[k + 2] : wv[k];
            float send = b3 ? wv[k] : wv[k + 2];
            uv[k] = keep + __shfl_xor_sync(0xffffffffu, send, 8);
        }
        float z;
        {
            float keep = b2 ? uv[1] : uv[0];
            float send = b2 ? uv[0] : uv[1];
            z = keep + __shfl_xor_sync(0xffffffffu, send, 4);
        }
        z += __shfl_xor_sync(0xffffffffu, z, 2);
        z += __shfl_xor_sync(0xffffffffu, z, 1);

        // lane-parallel nonlinearity (2 MUFU for all 8 gates of this warp)
        float x = z + xig;
        float sarg = (gate == 2) ? 2.f * x : x;
        float e = __expf(-sarg);
        float rr = __fdividef(1.f, 1.f + e);
        float y = (gate == 2) ? (2.f * rr - 1.f) : rr;

        float iA = __shfl_sync(0xffffffffu, y, 0);
        float fA = __shfl_sync(0xffffffffu, y, 4);
        float gA = __shfl_sync(0xffffffffu, y, 8);
        float oA = __shfl_sync(0xffffffffu, y, 12);
        float iB = __shfl_sync(0xffffffffu, y, 16);
        float fB = __shfl_sync(0xffffffffu, y, 20);
        float gB = __shfl_sync(0xffffffffu, y, 24);
        float oB = __shfl_sync(0xffffffffu, y, 28);
        cA = fA * cA + iA * gA;
        cB = fB * cB + iB * gB;

        // lane-parallel tanh(c)
        float xc = (ld & 1) ? cB : cA;
        float ec = __expf(-2.f * xc);
        float tc = __fdividef(2.f, 1.f + ec) - 1.f;
        float tA = __shfl_sync(0xffffffffu, tc, 0);
        float tB = __shfl_sync(0xffffffffu, tc, 1);
        float hA = oA * tA, hB = oB * tB;

        // broadcast h to all 16 CTAs' smem (write parity s&1)
        int pw = s & 1;
        if (st_valid) {
            float hv = usel ? hB : hA;
            unsigned addr = st_off0 + (unsigned)(pw * HPAD * 4);
            asm volatile("st.shared::cluster.f32 [%0], %1;" :: "r"(addr), "f"(hv) : "memory");
        }
        if (ld == 0) {
            float* o = Hout + (size_t)t * 800 + dir * HID;
            o[guA] = hA;
            if (vB) o[guB] = hB;
        }
        asm volatile("barrier.cluster.arrive.aligned;" ::: "memory");
        asm volatile("barrier.cluster.wait.aligned;"  ::: "memory");
    }
}

// ---------------- head/dep projections ----------------
__global__ void headdep_k(const float* __restrict__ fw)
{
    int i = blockIdx.x;
    const float* hr = g_H1 + (size_t)i * 800;
    float a = 0.f, b = 0.f;
    for (int k = threadIdx.x; k < 800; k += 256) {
        float h = hr[k];
        a += h * __ldg(fw + k);
        b += h * __ldg(fw + 800 + k);
    }
#pragma unroll
    for (int o = 16; o; o >>= 1) {
        a += __shfl_xor_sync(0xffffffffu, a, o);
        b += __shfl_xor_sync(0xffffffffu, b, o);
    }
    __shared__ float sa[8], sb[8];
    int w = threadIdx.x >> 5, ld = threadIdx.x & 31;
    if (ld == 0) { sa[w] = a; sb[w] = b; }
    __syncthreads();
    if (threadIdx.x == 0) {
        float A = 0.f, B = 0.f;
#pragma unroll
        for (int q = 0; q < 8; ++q) { A += sa[q]; B += sb[q]; }
        g_sv[i] = A; g_tv[i] = B;
    }
}

// ---------------- pairwise scores ----------------
__global__ void scores_k(const float* __restrict__ fb, float* __restrict__ out)
{
    int i = blockIdx.x, jj = threadIdx.x;
    out[(size_t)i * LQ + jj] = tanhf(g_sv[i] + g_tv[jj] + fb[0]);
}

// ---------------- launch ----------------
extern "C" void kernel_launch(void* const* d_in, const int* in_sizes, int n_in,
                              void* d_out, int out_size)
{
    int base = (in_sizes[2] == 1) ? 3 : 2;
    const int*   wi   = (const int*)d_in[0];
    const int*   ti   = (const int*)d_in[1];
    const float* we   = (const float*)d_in[base + 0];
    const float* te   = (const float*)d_in[base + 1];
    const float* wih0 = (const float*)d_in[base + 2];
    const float* whh0 = (const float*)d_in[base + 3];
    const float* bih0 = (const float*)d_in[base + 4];
    const float* bhh0 = (const float*)d_in[base + 5];
    const float* wih1 = (const float*)d_in[base + 6];
    const float* whh1 = (const float*)d_in[base + 7];
    const float* bih1 = (const float*)d_in[base + 8];
    const float* bhh1 = (const float*)d_in[base + 9];
    const float* fw   = (const float*)d_in[base + 10];
    const float* fb   = (const float*)d_in[base + 11];
    float* out = (float*)d_out;

    // allow cluster size 16 (nonportable)
    cudaFuncSetAttribute(scan_k, cudaFuncAttributeNonPortableClusterSizeAllowed, 1);

    embed_k<<<LQ, 128>>>(wi, ti, we, te);
    dim3 gg(GATES / 64, LQ / 64, 2);
    gemm_k<<<gg, 256>>>(0, wih0, bih0, bhh0);
    scan_k<<<2 * CLUST, THREADS>>>(0, whh0);
    gemm_k<<<gg, 256>>>(1, wih1, bih1, bhh1);
    scan_k<<<2 * CLUST, THREADS>>>(1, whh1);
    headdep_k<<<LQ, 256>>>(fw);
    scores_k<<<LQ, LQ>>>(fb, out);
}